// round 2
// baseline (speedup 1.0000x reference)
#include <cuda_runtime.h>

#define NN 50000
#define EE 800000
#define DD 96
#define NV4 (NN * DD / 4)   // float4 count of an [N,96] array

// ---------------- scratch (device globals; no allocation allowed) ----------
__device__ __align__(256) float g_deg[NN];
__device__ __align__(256) float g_dis[NN];
__device__ __align__(256) float g_norm[EE];
__device__ __align__(256) float g_T1[NN * DD];
__device__ __align__(256) float g_P[NN * DD];
__device__ __align__(256) float g_acc[NN * DD];   // pre-BN output
__device__ __align__(256) float g_colsum[DD];
__device__ __align__(256) float g_colsumsq[DD];
__device__ __align__(256) float g_scale[DD];
__device__ __align__(256) float g_shift[DD];

// ---------------- zero scratch ---------------------------------------------
__global__ void zero_kernel() {
    int tid = blockIdx.x * blockDim.x + threadIdx.x;
    int stride = gridDim.x * blockDim.x;
    float4* t1 = reinterpret_cast<float4*>(g_T1);
    float4* p  = reinterpret_cast<float4*>(g_P);
    float4 z = make_float4(0.f, 0.f, 0.f, 0.f);
    for (int i = tid; i < NV4; i += stride) { t1[i] = z; p[i] = z; }
    for (int i = tid; i < NN; i += stride) g_deg[i] = 0.f;
    if (tid < DD) { g_colsum[tid] = 0.f; g_colsumsq[tid] = 0.f; }
}

// ---------------- degree / normalization -----------------------------------
__global__ void deg_kernel(const int* __restrict__ ei) {
    int e = blockIdx.x * blockDim.x + threadIdx.x;
    if (e >= EE) return;
    int r = ei[e], c = ei[EE + e];
    if (r != c) atomicAdd(&g_deg[r], 1.0f);
}

__global__ void dis_kernel() {
    int i = blockIdx.x * blockDim.x + threadIdx.x;
    if (i >= NN) return;
    float d = g_deg[i];
    g_dis[i] = (d > 0.f) ? rsqrtf(fmaxf(d, 1e-12f)) : 0.f;
}

__global__ void norm_kernel(const int* __restrict__ ei) {
    int e = blockIdx.x * blockDim.x + threadIdx.x;
    if (e >= EE) return;
    int r = ei[e], c = ei[EE + e];
    g_norm[e] = (r != c) ? (-g_dis[r] * g_dis[c]) : 0.f;
}

// ---------------- SpMM: dst[col] += norm[e] * src[row] ---------------------
// Warp handles 4 edges; 8 lanes per edge; each lane moves 3 float4 (96 floats).
// Scatter via red.global.add.v4.f32 (vector reduction, no return).
__global__ void spmm_kernel(int pass, const float* __restrict__ x,
                            const int* __restrict__ ei) {
    const float4* src = (pass == 0) ? reinterpret_cast<const float4*>(x)
                                    : reinterpret_cast<const float4*>(g_T1);
    float* dst = (pass == 0) ? g_T1 : g_P;

    int warp_id = (blockIdx.x * blockDim.x + threadIdx.x) >> 5;
    int lane = threadIdx.x & 31;
    int e = warp_id * 4 + (lane >> 3);
    if (e >= EE) return;

    float nrm = g_norm[e];
    if (nrm == 0.f) return;
    int r = ei[e], c = ei[EE + e];
    int chunk = lane & 7;

    const float4* srow = src + r * (DD / 4);
    float* drow = dst + c * DD;

#pragma unroll
    for (int s = 0; s < 3; s++) {
        int idx = chunk + 8 * s;          // 0..23
        float4 v = __ldg(srow + idx);
        float a = nrm * v.x, b = nrm * v.y, cc = nrm * v.z, d = nrm * v.w;
        float* addr = drow + idx * 4;     // 16B aligned
        asm volatile("red.global.add.v4.f32 [%0], {%1, %2, %3, %4};"
                     :: "l"(addr), "f"(a), "f"(b), "f"(cc), "f"(d)
                     : "memory");
    }
}

// ---------------- fused GEMM + bias + column-stat accumulation -------------
// out = x@W0 + T1@W1 + (2P - x)@W2 + bias ; colsum/colsumsq for BN.
// blockDim = 192 (tx = tid%24 -> 4 j's stride 24; ty = tid/24 -> 8 rows each).
// 64 rows per block. W transposed into smem with stride 100 (conflict-free
// LDS.128 per quarter-warp).
#define GEMM_THREADS 192
#define RPB 64              // rows per block
#define WS_STRIDE 100
#define WS_MAT (DD * WS_STRIDE)                 // 9600 floats per matrix
#define SMEM_FLOATS (3 * WS_MAT + DD + 3 * RPB * DD)
#define SMEM_BYTES (SMEM_FLOATS * 4)

__global__ __launch_bounds__(GEMM_THREADS, 1)
void gemm_kernel(const float* __restrict__ x, const float* __restrict__ W,
                 const float* __restrict__ bias) {
    extern __shared__ float smem[];
    float* Ws  = smem;                   // [3][96*100]
    float* bs  = Ws + 3 * WS_MAT;        // [96]
    float* xs  = bs + DD;                // [64*96]
    float* t1s = xs + RPB * DD;          // [64*96]
    float* t2s = t1s + RPB * DD;         // [64*96]

    int tid = threadIdx.x;

    // stage W transposed: Ws[kk][j*100 + k] = W[kk][k][j]
    for (int i = tid; i < 3 * DD * DD; i += GEMM_THREADS) {
        int kk = i / (DD * DD);
        int rem = i - kk * DD * DD;
        int k = rem / DD;
        int j = rem - k * DD;
        Ws[kk * WS_MAT + j * WS_STRIDE + k] = W[i];
    }
    if (tid < DD) bs[tid] = bias[tid];

    int base = blockIdx.x * RPB;

    // stage 64 rows of x, T1 and T2 = 2P - x (float4)
    {
        const float4* x4  = reinterpret_cast<const float4*>(x);
        const float4* t14 = reinterpret_cast<const float4*>(g_T1);
        const float4* p4  = reinterpret_cast<const float4*>(g_P);
        float4* xs4  = reinterpret_cast<float4*>(xs);
        float4* t1s4 = reinterpret_cast<float4*>(t1s);
        float4* t2s4 = reinterpret_cast<float4*>(t2s);
        for (int i = tid; i < RPB * (DD / 4); i += GEMM_THREADS) {
            int r = i / (DD / 4);
            int row = base + r;
            float4 xv = make_float4(0.f, 0.f, 0.f, 0.f);
            float4 t1v = xv, t2v = xv;
            if (row < NN) {
                int gi = row * (DD / 4) + (i - r * (DD / 4));
                xv = __ldg(x4 + gi);
                t1v = t14[gi];
                float4 pv = p4[gi];
                t2v = make_float4(2.f * pv.x - xv.x, 2.f * pv.y - xv.y,
                                  2.f * pv.z - xv.z, 2.f * pv.w - xv.w);
            }
            xs4[i] = xv; t1s4[i] = t1v; t2s4[i] = t2v;
        }
    }
    __syncthreads();

    int tx = tid % 24;           // j in {tx, tx+24, tx+48, tx+72}
    int ty = tid / 24;           // rows [base + ty*8, base + ty*8 + 8)

    float acc[8][4];
#pragma unroll
    for (int r = 0; r < 8; r++)
#pragma unroll
        for (int jj = 0; jj < 4; jj++)
            acc[r][jj] = bs[tx + jj * 24];

    const float* xrow  = xs  + ty * 8 * DD;
    const float* t1row = t1s + ty * 8 * DD;
    const float* t2row = t2s + ty * 8 * DD;

    for (int k = 0; k < DD; k += 4) {
        float4 w0[4], w1[4], w2[4];
#pragma unroll
        for (int jj = 0; jj < 4; jj++) {
            int j = tx + jj * 24;
            w0[jj] = *reinterpret_cast<const float4*>(&Ws[0 * WS_MAT + j * WS_STRIDE + k]);
            w1[jj] = *reinterpret_cast<const float4*>(&Ws[1 * WS_MAT + j * WS_STRIDE + k]);
            w2[jj] = *reinterpret_cast<const float4*>(&Ws[2 * WS_MAT + j * WS_STRIDE + k]);
        }
#pragma unroll
        for (int r = 0; r < 8; r++) {
            float4 xv = *reinterpret_cast<const float4*>(&xrow[r * DD + k]);
            float4 av = *reinterpret_cast<const float4*>(&t1row[r * DD + k]);
            float4 bv = *reinterpret_cast<const float4*>(&t2row[r * DD + k]);
#pragma unroll
            for (int jj = 0; jj < 4; jj++) {
                float s = acc[r][jj];
                s += xv.x * w0[jj].x; s += xv.y * w0[jj].y;
                s += xv.z * w0[jj].z; s += xv.w * w0[jj].w;
                s += av.x * w1[jj].x; s += av.y * w1[jj].y;
                s += av.z * w1[jj].z; s += av.w * w1[jj].w;
                s += bv.x * w2[jj].x; s += bv.y * w2[jj].y;
                s += bv.z * w2[jj].z; s += bv.w * w2[jj].w;
                acc[r][jj] = s;
            }
        }
    }

    // epilogue: write pre-BN output + accumulate column stats
#pragma unroll
    for (int jj = 0; jj < 4; jj++) {
        int j = tx + jj * 24;
        float s = 0.f, s2 = 0.f;
#pragma unroll
        for (int r = 0; r < 8; r++) {
            int row = base + ty * 8 + r;
            if (row < NN) {
                float v = acc[r][jj];
                g_acc[row * DD + j] = v;
                s += v; s2 += v * v;
            }
        }
        atomicAdd(&g_colsum[j], s);
        atomicAdd(&g_colsumsq[j], s2);
    }
}

// ---------------- BatchNorm finalize ---------------------------------------
__global__ void bn_stats_kernel(const float* __restrict__ gamma,
                                const float* __restrict__ beta) {
    int j = threadIdx.x;
    if (j >= DD) return;
    float inv_n = 1.0f / (float)NN;
    float mean = g_colsum[j] * inv_n;
    float var = g_colsumsq[j] * inv_n - mean * mean;
    var = fmaxf(var, 0.f);
    float istd = rsqrtf(var + 1e-5f);
    float sc = gamma[j] * istd;
    g_scale[j] = sc;
    g_shift[j] = beta[j] - mean * sc;
}

__global__ void bn_apply_kernel(float* __restrict__ out) {
    __shared__ float sc[DD], sh[DD];
    if (threadIdx.x < DD) {
        sc[threadIdx.x] = g_scale[threadIdx.x];
        sh[threadIdx.x] = g_shift[threadIdx.x];
    }
    __syncthreads();
    int tid = blockIdx.x * blockDim.x + threadIdx.x;
    int stride = gridDim.x * blockDim.x;
    const float4* in4 = reinterpret_cast<const float4*>(g_acc);
    float4* o4 = reinterpret_cast<float4*>(out);
    for (int i = tid; i < NV4; i += stride) {
        int c4 = i % (DD / 4);
        int j = c4 * 4;
        float4 v = in4[i];
        o4[i] = make_float4(v.x * sc[j]     + sh[j],
                            v.y * sc[j + 1] + sh[j + 1],
                            v.z * sc[j + 2] + sh[j + 2],
                            v.w * sc[j + 3] + sh[j + 3]);
    }
}

// ---------------- launch ----------------------------------------------------
extern "C" void kernel_launch(void* const* d_in, const int* in_sizes, int n_in,
                              void* d_out, int out_size) {
    const float* x     = (const float*)d_in[0];
    const int*   ei    = (const int*)d_in[1];
    const float* W     = (const float*)d_in[2];
    const float* bias  = (const float*)d_in[3];
    const float* gamma = (const float*)d_in[4];
    const float* beta  = (const float*)d_in[5];
    float* out = (float*)d_out;

    cudaFuncSetAttribute(gemm_kernel,
                         cudaFuncAttributeMaxDynamicSharedMemorySize, SMEM_BYTES);

    zero_kernel<<<2048, 256>>>();
    deg_kernel<<<(EE + 255) / 256, 256>>>(ei);
    dis_kernel<<<(NN + 255) / 256, 256>>>();
    norm_kernel<<<(EE + 255) / 256, 256>>>(ei);
    // prop 1: T1 = L_hat @ x
    spmm_kernel<<<EE / 32, 256>>>(0, x, ei);
    // prop 2: P = L_hat @ T1  (T2 = 2P - x computed in GEMM)
    spmm_kernel<<<EE / 32, 256>>>(1, x, ei);
    gemm_kernel<<<(NN + RPB - 1) / RPB, GEMM_THREADS, SMEM_BYTES>>>(x, W, bias);
    bn_stats_kernel<<<1, 128>>>(gamma, beta);
    bn_apply_kernel<<<2048, 256>>>(out);
}